// round 10
// baseline (speedup 1.0000x reference)
#include <cuda_runtime.h>
#include <cuda_bf16.h>
#include <math.h>
#include <stdint.h>

// ---------------- problem constants ----------------
#define BB   64
#define SS   64
#define TT   32
#define EE   512
#define UU   1024
#define G4   (4*UU)      // 4096
#define U2   (2*UU)      // 2048
#define VD_  32000

// ---------------- device scratch (allocation-free contract) ----------------
__device__ __nv_bfloat16 g_XembEHi[BB*SS*EE];
__device__ __nv_bfloat16 g_XembELo[BB*SS*EE];
__device__ __nv_bfloat16 g_XembDHi[BB*TT*EE];
__device__ __nv_bfloat16 g_XembDLo[BB*TT*EE];
__device__ __nv_bfloat16 g_WeHi[G4*EE];
__device__ __nv_bfloat16 g_WeLo[G4*EE];
__device__ __nv_bfloat16 g_WidHi[G4*EE];
__device__ __nv_bfloat16 g_WidLo[G4*EE];
__device__ __nv_bfloat16 g_WdHi[(size_t)VD_*U2];
__device__ __nv_bfloat16 g_WdLo[(size_t)VD_*U2];
__device__ __nv_bfloat16 g_hcHi[(size_t)BB*TT*U2];
__device__ __nv_bfloat16 g_hcLo[(size_t)BB*TT*U2];

// recurrence: reordered bf16 weights (CTA-sliced, gate-interleaved rows)
__device__ __nv_bfloat16 g_WreHi[(size_t)G4*UU];          // enc: row' = cta*32 + g*8 + uu
__device__ __nv_bfloat16 g_WreLo[(size_t)G4*UU];
__device__ __nv_bfloat16 g_WrdHi[(size_t)(UU+G4)*UU];     // dec: row' = cta*40 + [q:0..7 | 8+g*8+uu]
__device__ __nv_bfloat16 g_WrdLo[(size_t)(UU+G4)*UU];
// h double-buffered by step parity: read [par], write [par^1]  (fixes cross-CTA race)
__device__ __nv_bfloat16 g_hHi[2][BB*UU];
__device__ __nv_bfloat16 g_hLo[2][BB*UU];

__device__ float g_Xe[(size_t)BB*SS*G4];            // x@W_ih_e^T + biases
__device__ float g_Xd[(size_t)BB*TT*G4];
__device__ float g_o [(size_t)BB*SS*UU];            // encoder outputs (fp32, for attention)
__device__ float g_c [BB*UU];
__device__ float g_q [2][BB*UU];                    // double-buffered q = h@Wa^T
__device__ float g_hc[(size_t)BB*TT*U2];            // [b*T+t][ctx|h]

// ---------------- helpers ----------------
__device__ __forceinline__ float sigf(float x) { return 1.f / (1.f + expf(-x)); }

__device__ __forceinline__ void cp16(void* dst, const void* src) {
    uint32_t a;
    asm("{ .reg .u64 t; cvta.to.shared.u64 t, %1; cvt.u32.u64 %0, t; }"
        : "=r"(a) : "l"(dst));
    asm volatile("cp.async.cg.shared.global [%0], [%1], 16;" :: "r"(a), "l"(src));
}

__device__ __forceinline__ void mma16816(float* c, const uint32_t* a, const uint32_t* b) {
    asm volatile(
        "mma.sync.aligned.m16n8k16.row.col.f32.bf16.bf16.f32 "
        "{%0,%1,%2,%3}, {%4,%5,%6,%7}, {%8,%9}, {%0,%1,%2,%3};"
        : "+f"(c[0]), "+f"(c[1]), "+f"(c[2]), "+f"(c[3])
        : "r"(a[0]), "r"(a[1]), "r"(a[2]), "r"(a[3]), "r"(b[0]), "r"(b[1]));
}

__device__ __forceinline__ void split1(float x, __nv_bfloat16& h, __nv_bfloat16& l) {
    h = __float2bfloat16(x);
    l = __float2bfloat16(x - __bfloat162float(h));
}

// ---------------- generic fp32 -> bf16 hi/lo split ----------------
__global__ void k_split4(const float4* __restrict__ src,
                         __nv_bfloat162* __restrict__ hi,
                         __nv_bfloat162* __restrict__ lo, int n4)
{
    int gid = blockIdx.x * blockDim.x + threadIdx.x;
    if (gid >= n4) return;
    float4 v = src[gid];
    __nv_bfloat16 hx, hy, hz, hw, lx, ly, lz, lw;
    split1(v.x, hx, lx); split1(v.y, hy, ly);
    split1(v.z, hz, lz); split1(v.w, hw, lw);
    __nv_bfloat162 a; a.x = hx; a.y = hy;
    __nv_bfloat162 b; b.x = hz; b.y = hw;
    __nv_bfloat162 c; c.x = lx; c.y = ly;
    __nv_bfloat162 d; d.x = lz; d.y = lw;
    hi[gid * 2] = a; hi[gid * 2 + 1] = b;
    lo[gid * 2] = c; lo[gid * 2 + 1] = d;
}

// ---------------- reorder + split for recurrence weights ----------------
__global__ void k_split_reord_enc(const float4* __restrict__ W) {
    int gid = blockIdx.x * blockDim.x + threadIdx.x;   // G4 * 256
    int rp = gid >> 8, c = gid & 255;
    int cta = rp >> 5, rr = rp & 31;
    int g = rr >> 3, uu = rr & 7;
    int orig = g * UU + cta * 8 + uu;
    float4 v = W[(size_t)orig * 256 + c];
    __nv_bfloat16 hx, hy, hz, hw, lx, ly, lz, lw;
    split1(v.x, hx, lx); split1(v.y, hy, ly);
    split1(v.z, hz, lz); split1(v.w, hw, lw);
    __nv_bfloat162 a; a.x = hx; a.y = hy;
    __nv_bfloat162 b; b.x = hz; b.y = hw;
    __nv_bfloat162 cc; cc.x = lx; cc.y = ly;
    __nv_bfloat162 dd; dd.x = lz; dd.y = lw;
    ((__nv_bfloat162*)g_WreHi)[gid * 2] = a; ((__nv_bfloat162*)g_WreHi)[gid * 2 + 1] = b;
    ((__nv_bfloat162*)g_WreLo)[gid * 2] = cc; ((__nv_bfloat162*)g_WreLo)[gid * 2 + 1] = dd;
}

__global__ void k_split_reord_dec(const float4* __restrict__ Wa,
                                  const float4* __restrict__ Whh) {
    int gid = blockIdx.x * blockDim.x + threadIdx.x;   // (UU+G4) * 256
    int rp = gid >> 8, c = gid & 255;
    int cta = rp / 40, rr = rp % 40;
    const float4* src;
    int orig;
    if (rr < 8) { src = Wa;  orig = cta * 8 + rr; }
    else {
        int g = (rr - 8) >> 3, uu = (rr - 8) & 7;
        src = Whh; orig = g * UU + cta * 8 + uu;
    }
    float4 v = src[(size_t)orig * 256 + c];
    __nv_bfloat16 hx, hy, hz, hw, lx, ly, lz, lw;
    split1(v.x, hx, lx); split1(v.y, hy, ly);
    split1(v.z, hz, lz); split1(v.w, hw, lw);
    __nv_bfloat162 a; a.x = hx; a.y = hy;
    __nv_bfloat162 b; b.x = hz; b.y = hw;
    __nv_bfloat162 cc; cc.x = lx; cc.y = ly;
    __nv_bfloat162 dd; dd.x = lz; dd.y = lw;
    ((__nv_bfloat162*)g_WrdHi)[gid * 2] = a; ((__nv_bfloat162*)g_WrdHi)[gid * 2 + 1] = b;
    ((__nv_bfloat162*)g_WrdLo)[gid * 2] = cc; ((__nv_bfloat162*)g_WrdLo)[gid * 2 + 1] = dd;
}

// ---------------- embedding gathers (write bf16 hi/lo) ----------------
__global__ void k_gather_enc(const int* __restrict__ x, const float* __restrict__ emb) {
    int gid = blockIdx.x * blockDim.x + threadIdx.x;      // BB*SS*(EE/4)
    const int E4 = EE / 4;
    int r = gid / E4, c = gid % E4;
    float4 v = ((const float4*)emb)[(size_t)x[r] * E4 + c];
    __nv_bfloat16 hx, hy, hz, hw, lx, ly, lz, lw;
    split1(v.x, hx, lx); split1(v.y, hy, ly);
    split1(v.z, hz, lz); split1(v.w, hw, lw);
    size_t pi = (size_t)r * (EE / 2) + c * 2;
    __nv_bfloat162 a; a.x = hx; a.y = hy; ((__nv_bfloat162*)g_XembEHi)[pi] = a;
    __nv_bfloat162 b; b.x = hz; b.y = hw; ((__nv_bfloat162*)g_XembEHi)[pi + 1] = b;
    __nv_bfloat162 cc; cc.x = lx; cc.y = ly; ((__nv_bfloat162*)g_XembELo)[pi] = cc;
    __nv_bfloat162 dd; dd.x = lz; dd.y = lw; ((__nv_bfloat162*)g_XembELo)[pi + 1] = dd;
}

__global__ void k_gather_dec(const int* __restrict__ y, const float* __restrict__ emb) {
    int gid = blockIdx.x * blockDim.x + threadIdx.x;      // BB*TT*(EE/4)
    const int E4 = EE / 4;
    int r = gid / E4, c = gid % E4;
    int b = r / TT, t = r % TT;
    int id = y[b * (TT + 1) + t];
    float4 v = ((const float4*)emb)[(size_t)id * E4 + c];
    __nv_bfloat16 hx, hy, hz, hw, lx, ly, lz, lw;
    split1(v.x, hx, lx); split1(v.y, hy, ly);
    split1(v.z, hz, lz); split1(v.w, hw, lw);
    size_t pi = (size_t)r * (EE / 2) + c * 2;
    __nv_bfloat162 a; a.x = hx; a.y = hy; ((__nv_bfloat162*)g_XembDHi)[pi] = a;
    __nv_bfloat162 b2; b2.x = hz; b2.y = hw; ((__nv_bfloat162*)g_XembDHi)[pi + 1] = b2;
    __nv_bfloat162 cc; cc.x = lx; cc.y = ly; ((__nv_bfloat162*)g_XembDLo)[pi] = cc;
    __nv_bfloat162 dd; dd.x = lz; dd.y = lw; ((__nv_bfloat162*)g_XembDLo)[pi + 1] = dd;
}

__global__ void k_init_state() {
    int gid = blockIdx.x * blockDim.x + threadIdx.x;
    if (gid < BB * UU) {
        g_c[gid] = 0.f;
        g_hHi[0][gid] = __float2bfloat16(0.f);
        g_hLo[0][gid] = __float2bfloat16(0.f);
        g_hHi[1][gid] = __float2bfloat16(0.f);
        g_hLo[1][gid] = __float2bfloat16(0.f);
    }
}

// ---------------- HMMA bf16x2-compensated GEMM (big, 128x128 tile) ----------------
#define PITCH   80
#define ARR_SZ  (128 * PITCH)           // 10240
#define STG_SZ  (4 * ARR_SZ)            // 40960
#define OFF_AHI 0
#define OFF_ALO ARR_SZ
#define OFF_BHI (2 * ARR_SZ)
#define OFF_BLO (3 * ARR_SZ)
#define SMEM_DYN (2 * STG_SZ)           // 80 KB

template <int MODE>
__global__ void __launch_bounds__(256)
k_hmma(const __nv_bfloat16* __restrict__ Ahi, const __nv_bfloat16* __restrict__ Alo,
       const __nv_bfloat16* __restrict__ Bhi, const __nv_bfloat16* __restrict__ Blo,
       const float* __restrict__ bias1, const float* __restrict__ bias2,
       float* __restrict__ C, int M, int N, int K)
{
    extern __shared__ __align__(16) char smem[];

    const int tid = threadIdx.x;
    const int wid = tid >> 5, lane = tid & 31;
    const int gq = lane >> 2, tq = lane & 3;
    const int wm = (wid >> 2) * 64;
    const int wn = (wid & 3) * 32;
    const int bm = blockIdx.y * 128, bn = blockIdx.x * 128;
    const int nk = K >> 5;

    const __nv_bfloat16* gsrc[4] = {Ahi, Alo, Bhi, Blo};

    auto load_stage = [&](int kc) {
        char* base = smem + (kc & 1) * STG_SZ;
        int k0 = kc << 5;
#pragma unroll
        for (int i = 0; i < 8; i++) {
            int e = tid + i * 256;
            int arr = e >> 9;
            int r = (e >> 2) & 127;
            int seg = e & 3;
            int grow = (arr < 2 ? bm : bn) + r;
            const __nv_bfloat16* src = gsrc[arr] + (size_t)grow * K + k0 + seg * 8;
            cp16(base + arr * ARR_SZ + r * PITCH + seg * 16, src);
        }
        asm volatile("cp.async.commit_group;");
    };

    float acc[4][4][4];
#pragma unroll
    for (int i = 0; i < 4; i++)
#pragma unroll
        for (int j = 0; j < 4; j++)
#pragma unroll
            for (int q = 0; q < 4; q++) acc[i][j][q] = 0.f;

    load_stage(0);

    for (int kc = 0; kc < nk; kc++) {
        if (kc + 1 < nk) {
            load_stage(kc + 1);
            asm volatile("cp.async.wait_group 1;");
        } else {
            asm volatile("cp.async.wait_group 0;");
        }
        __syncthreads();

        const char* base = smem + (kc & 1) * STG_SZ;
#pragma unroll
        for (int kk = 0; kk < 2; kk++) {
            const int kb = kk * 32;
            uint32_t ah[4][4], al[4][4], bh[4][2], bl[4][2];
#pragma unroll
            for (int i = 0; i < 4; i++) {
                int r0 = wm + i * 16 + gq;
                const char* pa = base + kb + 4 * tq;
                ah[i][0] = *(const uint32_t*)(pa + OFF_AHI + r0 * PITCH);
                ah[i][1] = *(const uint32_t*)(pa + OFF_AHI + (r0 + 8) * PITCH);
                ah[i][2] = *(const uint32_t*)(pa + OFF_AHI + r0 * PITCH + 16);
                ah[i][3] = *(const uint32_t*)(pa + OFF_AHI + (r0 + 8) * PITCH + 16);
                al[i][0] = *(const uint32_t*)(pa + OFF_ALO + r0 * PITCH);
                al[i][1] = *(const uint32_t*)(pa + OFF_ALO + (r0 + 8) * PITCH);
                al[i][2] = *(const uint32_t*)(pa + OFF_ALO + r0 * PITCH + 16);
                al[i][3] = *(const uint32_t*)(pa + OFF_ALO + (r0 + 8) * PITCH + 16);
            }
#pragma unroll
            for (int j = 0; j < 4; j++) {
                int rb = wn + j * 8 + gq;
                const char* pb = base + kb + 4 * tq;
                bh[j][0] = *(const uint32_t*)(pb + OFF_BHI + rb * PITCH);
                bh[j][1] = *(const uint32_t*)(pb + OFF_BHI + rb * PITCH + 16);
                bl[j][0] = *(const uint32_t*)(pb + OFF_BLO + rb * PITCH);
                bl[j][1] = *(const uint32_t*)(pb + OFF_BLO + rb * PITCH + 16);
            }
#pragma unroll
            for (int i = 0; i < 4; i++)
#pragma unroll
                for (int j = 0; j < 4; j++) {
                    mma16816(acc[i][j], ah[i], bh[j]);
                    mma16816(acc[i][j], ah[i], bl[j]);
                    mma16816(acc[i][j], al[i], bh[j]);
                }
        }
        __syncthreads();
    }

#pragma unroll
    for (int i = 0; i < 4; i++) {
        int r0 = bm + wm + i * 16 + gq;
        if (MODE == 0) {
#pragma unroll
            for (int j = 0; j < 4; j++) {
                int col = bn + wn + j * 8 + 2 * tq;
                float b0 = bias1[col] + (bias2 ? bias2[col] : 0.f);
                float b1 = bias1[col + 1] + (bias2 ? bias2[col + 1] : 0.f);
                float2 v0 = make_float2(acc[i][j][0] + b0, acc[i][j][1] + b1);
                float2 v1 = make_float2(acc[i][j][2] + b0, acc[i][j][3] + b1);
                *(float2*)(C + (size_t)r0 * N + col) = v0;
                *(float2*)(C + (size_t)(r0 + 8) * N + col) = v1;
            }
        } else {
            float bv0 = bias1[r0];
            float bv1 = bias1[r0 + 8];
#pragma unroll
            for (int j = 0; j < 4; j++) {
                int col = bn + wn + j * 8 + 2 * tq;
                int b = col >> 5, t = col & 31;
                float* p0 = C + ((size_t)b * VD_ + r0) * 32 + t;
                float* p1 = C + ((size_t)b * VD_ + r0 + 8) * 32 + t;
                *(float2*)p0 = make_float2(acc[i][j][0] + bv0, acc[i][j][1] + bv0);
                *(float2*)p1 = make_float2(acc[i][j][2] + bv1, acc[i][j][3] + bv1);
            }
        }
    }
}

// ---------------- attention body (shared by decoder step + tail) ----------------
__device__ __forceinline__ void attn_body(int b, int ta, const float* __restrict__ ba,
                                          float* scratch)
{
    float* qs = scratch;          // 1024
    float* sc = scratch + UU;     // 65 (sc[SS] holds 1/sum)
    int tid = threadIdx.x;

    const float* qrow = g_q[ta & 1] + (size_t)b * UU;
    for (int u = tid; u < UU; u += 256) qs[u] = qrow[u] + ba[u];
    __syncthreads();

    int w = tid >> 5, lane = tid & 31;
    const float* ob = g_o + (size_t)b * SS * UU;
    for (int s = w; s < SS; s += 8) {
        const float* os = ob + (size_t)s * UU;
        float acc = 0.f;
        for (int u = lane; u < UU; u += 32) acc = fmaf(qs[u], os[u], acc);
#pragma unroll
        for (int off = 16; off; off >>= 1) acc += __shfl_xor_sync(0xffffffffu, acc, off);
        if (lane == 0) sc[s] = acc;
    }
    __syncthreads();

    if (tid == 0) {
        float mx = sc[0];
#pragma unroll
        for (int s = 1; s < SS; s++) mx = fmaxf(mx, sc[s]);
        float sum = 0.f;
        for (int s = 0; s < SS; s++) { float e = expf(sc[s] - mx); sc[s] = e; sum += e; }
        sc[SS] = 1.f / sum;
    }
    __syncthreads();
    float inv = sc[SS];

    float* hcrow = g_hc + (size_t)(b * TT + ta) * U2;
    for (int u = tid; u < UU; u += 256) {
        float acc = 0.f;
#pragma unroll 8
        for (int s = 0; s < SS; s++) acc = fmaf(sc[s] * inv, ob[(size_t)s * UU + u], acc);
        hcrow[u] = acc;
    }
}

// ---------------- fused recurrence step: GEMM + gate (+ attention riders) ----------
// MODE 0 (encoder): grid 128, NR=32. Each CTA owns u-slice [cta*8, cta*8+8),
//   W rows ordered g*8+uu. Computes z(64x32), gates locally, writes o + h hi/lo.
// MODE 1 (decoder): grid 192, NR=40 (q rows 0..7 then z rows). Blocks 128..191
//   run attention for step t-1 (reads g_q[(t-1)&1]).
// h is double-buffered: read g_h*[t&1], write g_h*[(t&1)^1]. (Race fix.)
template <int MODE>
__global__ void __launch_bounds__(256)
k_rec_step(int t, const float* __restrict__ ba)
{
    constexpr int NR = MODE ? 40 : 32;
    constexpr int STG = (128 + 2 * NR) * 80;     // bytes per stage
    constexpr int OALO = 64 * 80;                // 5120
    constexpr int OBHI = 128 * 80;               // 10240
    constexpr int TOT = 512 + NR * 8;            // cp16 ops per stage

    __shared__ char sbuf[2][STG];
    __shared__ float zs[64 * 33];

    const int tid = threadIdx.x;
    const int par = t & 1;

    if (MODE == 1 && blockIdx.x >= 128) {
        if (t == 0) return;
        attn_body(blockIdx.x - 128, t - 1, ba, zs);
        return;
    }

    const int cta = blockIdx.x;
    const int wid = tid >> 5, lane = tid & 31;
    const int gq = lane >> 2, tq = lane & 3;
    const int mh = wid >> 2, nc = wid & 3;

    const __nv_bfloat16* Whi = MODE ? g_WrdHi : g_WreHi;
    const __nv_bfloat16* Wlo = MODE ? g_WrdLo : g_WreLo;
    const __nv_bfloat16* hHi = g_hHi[par];
    const __nv_bfloat16* hLo = g_hLo[par];
    const size_t wbase = (size_t)cta * NR * UU;

    auto load_stage = [&](int kc) {
        char* base = sbuf[kc & 1];
        int k0 = kc << 5;
#pragma unroll
        for (int i = 0; i < (TOT + 255) / 256; i++) {
            int e = tid + i * 256;
            if (e < TOT) {
                const __nv_bfloat16* src; char* dst;
                if (e < 512) {
                    int arr = e >> 8, r = (e >> 2) & 63, seg = e & 3;
                    src = (arr ? hLo : hHi) + r * UU + k0 + seg * 8;
                    dst = base + arr * OALO + r * 80 + seg * 16;
                } else {
                    int e2 = e - 512;
                    int arr = e2 >= NR * 4;
                    int idx = e2 - arr * NR * 4;
                    int r = idx >> 2, seg = idx & 3;
                    src = (arr ? Wlo : Whi) + wbase + (size_t)r * UU + k0 + seg * 8;
                    dst = base + OBHI + arr * (NR * 80) + r * 80 + seg * 16;
                }
                cp16(dst, src);
            }
        }
        asm volatile("cp.async.commit_group;");
    };

    float accz[2][4] = {};
    float accq[4] = {};

    load_stage(0);
    for (int kc = 0; kc < 32; kc++) {
        if (kc + 1 < 32) {
            load_stage(kc + 1);
            asm volatile("cp.async.wait_group 1;");
        } else {
            asm volatile("cp.async.wait_group 0;");
        }
        __syncthreads();

        const char* base = sbuf[kc & 1];
#pragma unroll
        for (int kk = 0; kk < 2; kk++) {
            const int kb = kk * 32;
            const char* pa = base + kb + 4 * tq;
            uint32_t ah[2][4], al[2][4];
#pragma unroll
            for (int i = 0; i < 2; i++) {
                int r0 = mh * 32 + i * 16 + gq;
                ah[i][0] = *(const uint32_t*)(pa + r0 * 80);
                ah[i][1] = *(const uint32_t*)(pa + (r0 + 8) * 80);
                ah[i][2] = *(const uint32_t*)(pa + r0 * 80 + 16);
                ah[i][3] = *(const uint32_t*)(pa + (r0 + 8) * 80 + 16);
                al[i][0] = *(const uint32_t*)(pa + OALO + r0 * 80);
                al[i][1] = *(const uint32_t*)(pa + OALO + (r0 + 8) * 80);
                al[i][2] = *(const uint32_t*)(pa + OALO + r0 * 80 + 16);
                al[i][3] = *(const uint32_t*)(pa + OALO + (r0 + 8) * 80 + 16);
            }
            {   // z tile: B row = (MODE? 8:0) + nc*8 + gq
                int rb = (MODE ? 8 : 0) + nc * 8 + gq;
                const char* pb = base + OBHI + rb * 80 + kb + 4 * tq;
                uint32_t bh[2], bl[2];
                bh[0] = *(const uint32_t*)(pb);
                bh[1] = *(const uint32_t*)(pb + 16);
                bl[0] = *(const uint32_t*)(pb + NR * 80);
                bl[1] = *(const uint32_t*)(pb + NR * 80 + 16);
#pragma unroll
                for (int i = 0; i < 2; i++) {
                    mma16816(accz[i], ah[i], bh);
                    mma16816(accz[i], ah[i], bl);
                    mma16816(accz[i], al[i], bh);
                }
            }
            if (MODE == 1 && nc < 2) {   // q tile: B rows 0..7, A frag = ah[nc]
                const char* pb = base + OBHI + gq * 80 + kb + 4 * tq;
                uint32_t bh[2], bl[2];
                bh[0] = *(const uint32_t*)(pb);
                bh[1] = *(const uint32_t*)(pb + 16);
                bl[0] = *(const uint32_t*)(pb + NR * 80);
                bl[1] = *(const uint32_t*)(pb + NR * 80 + 16);
                mma16816(accq, ah[nc], bh);
                mma16816(accq, ah[nc], bl);
                mma16816(accq, al[nc], bh);
            }
        }
        __syncthreads();
    }

    // ---- z -> SMEM ----
#pragma unroll
    for (int i = 0; i < 2; i++) {
        int b0 = mh * 32 + i * 16 + gq;
        int col = nc * 8 + 2 * tq;
        zs[b0 * 33 + col]           = accz[i][0];
        zs[b0 * 33 + col + 1]       = accz[i][1];
        zs[(b0 + 8) * 33 + col]     = accz[i][2];
        zs[(b0 + 8) * 33 + col + 1] = accz[i][3];
    }
    // ---- q -> global (decoder) ----
    if (MODE == 1 && nc < 2) {
        int f = mh * 2 + nc;
        int b0 = f * 16 + gq;
        int u0 = cta * 8 + 2 * tq;
        *(float2*)&g_q[t & 1][b0 * UU + u0]       = make_float2(accq[0], accq[1]);
        *(float2*)&g_q[t & 1][(b0 + 8) * UU + u0] = make_float2(accq[2], accq[3]);
    }
    __syncthreads();

    // ---- gate: 2 (b,uu) per thread ----
#pragma unroll
    for (int rep = 0; rep < 2; rep++) {
        int idx = tid + rep * 256;      // 0..511
        int b = idx >> 3, uu = idx & 7;
        int u = cta * 8 + uu;
        const float* xrow = MODE ? (g_Xd + (size_t)(b * TT + t) * G4)
                                 : (g_Xe + (size_t)(b * SS + t) * G4);
        float zi = zs[b * 33 + uu]      + xrow[u];
        float zf = zs[b * 33 + 8 + uu]  + xrow[UU + u];
        float zg = zs[b * 33 + 16 + uu] + xrow[2 * UU + u];
        float zo = zs[b * 33 + 24 + uu] + xrow[3 * UU + u];
        float c = g_c[b * UU + u];
        float cn = sigf(zf) * c + sigf(zi) * tanhf(zg);
        float hn = sigf(zo) * tanhf(cn);
        g_c[b * UU + u] = cn;
        __nv_bfloat16 hh, hl; split1(hn, hh, hl);
        g_hHi[par ^ 1][b * UU + u] = hh;
        g_hLo[par ^ 1][b * UU + u] = hl;
        if (MODE == 1) g_hc[(size_t)(b * TT + t) * U2 + UU + u] = hn;
        else           g_o [(size_t)(b * SS + t) * UU + u] = hn;
    }
}

__global__ void __launch_bounds__(256) k_attn_tail(int ta, const float* __restrict__ ba)
{
    __shared__ float scratch[1100];
    attn_body(blockIdx.x, ta, ba, scratch);
}

// ---------------- launch ----------------
extern "C" void kernel_launch(void* const* d_in, const int* in_sizes, int n_in,
                              void* d_out, int out_size)
{
    const int*   x       = (const int*)d_in[0];
    const int*   y       = (const int*)d_in[1];
    const float* enc_emb = (const float*)d_in[2];
    const float* dec_emb = (const float*)d_in[3];
    const float* W_ih_e  = (const float*)d_in[4];
    const float* W_hh_e  = (const float*)d_in[5];
    const float* b_ih_e  = (const float*)d_in[6];
    const float* b_hh_e  = (const float*)d_in[7];
    const float* Wa      = (const float*)d_in[8];
    const float* ba      = (const float*)d_in[9];
    const float* W_ih_d  = (const float*)d_in[10];
    const float* W_hh_d  = (const float*)d_in[11];
    const float* b_ih_d  = (const float*)d_in[12];
    const float* b_hh_d  = (const float*)d_in[13];
    const float* Wd      = (const float*)d_in[14];
    const float* bd      = (const float*)d_in[15];
    float* out = (float*)d_out;

    float *pXe, *pXd, *pHc;
    __nv_bfloat16 *pXeHi, *pXeLo, *pXdHi, *pXdLo, *pWeHi, *pWeLo, *pWidHi, *pWidLo;
    __nv_bfloat16 *pWdHi, *pWdLo, *pHcHi, *pHcLo;
    cudaGetSymbolAddress((void**)&pXe, g_Xe);
    cudaGetSymbolAddress((void**)&pXd, g_Xd);
    cudaGetSymbolAddress((void**)&pHc, g_hc);
    cudaGetSymbolAddress((void**)&pXeHi, g_XembEHi);
    cudaGetSymbolAddress((void**)&pXeLo, g_XembELo);
    cudaGetSymbolAddress((void**)&pXdHi, g_XembDHi);
    cudaGetSymbolAddress((void**)&pXdLo, g_XembDLo);
    cudaGetSymbolAddress((void**)&pWeHi, g_WeHi);
    cudaGetSymbolAddress((void**)&pWeLo, g_WeLo);
    cudaGetSymbolAddress((void**)&pWidHi, g_WidHi);
    cudaGetSymbolAddress((void**)&pWidLo, g_WidLo);
    cudaGetSymbolAddress((void**)&pWdHi, g_WdHi);
    cudaGetSymbolAddress((void**)&pWdLo, g_WdLo);
    cudaGetSymbolAddress((void**)&pHcHi, g_hcHi);
    cudaGetSymbolAddress((void**)&pHcLo, g_hcLo);

    cudaFuncSetAttribute(k_hmma<0>, cudaFuncAttributeMaxDynamicSharedMemorySize, SMEM_DYN);
    cudaFuncSetAttribute(k_hmma<1>, cudaFuncAttributeMaxDynamicSharedMemorySize, SMEM_DYN);

    // embeddings + init + weight splits
    k_gather_enc<<<BB * SS * (EE / 4) / 256, 256>>>(x, enc_emb);
    k_gather_dec<<<BB * TT * (EE / 4) / 256, 256>>>(y, dec_emb);
    k_init_state<<<BB * UU / 256, 256>>>();
    {
        int n4 = G4 * EE / 4;
        k_split4<<<(n4 + 255) / 256, 256>>>((const float4*)W_ih_e,
            (__nv_bfloat162*)pWeHi, (__nv_bfloat162*)pWeLo, n4);
        k_split4<<<(n4 + 255) / 256, 256>>>((const float4*)W_ih_d,
            (__nv_bfloat162*)pWidHi, (__nv_bfloat162*)pWidLo, n4);
    }
    // recurrence weights: reorder + split
    k_split_reord_enc<<<G4 * 256 / 256, 256>>>((const float4*)W_hh_e);
    k_split_reord_dec<<<(UU + G4) * 256 / 256, 256>>>((const float4*)Wa,
                                                      (const float4*)W_hh_d);
    {
        int n4 = (int)((size_t)VD_ * U2 / 4);
        k_split4<<<(n4 + 255) / 256, 256>>>((const float4*)Wd,
            (__nv_bfloat162*)pWdHi, (__nv_bfloat162*)pWdLo, n4);
    }

    // time-batched input projections (tensor pipe)
    k_hmma<0><<<dim3(G4 / 128, (BB * SS) / 128), 256, SMEM_DYN>>>(
        pXeHi, pXeLo, pWeHi, pWeLo, b_ih_e, b_hh_e, pXe, BB * SS, G4, EE);
    k_hmma<0><<<dim3(G4 / 128, (BB * TT) / 128), 256, SMEM_DYN>>>(
        pXdHi, pXdLo, pWidHi, pWidLo, b_ih_d, b_hh_d, pXd, BB * TT, G4, EE);

    // encoder: one fused GEMM+gate launch per step
    for (int t = 0; t < SS; t++)
        k_rec_step<0><<<128, 256>>>(t, ba);

    // decoder: one launch per step (GEMM+gate blocks + attention riders for t-1)
    for (int t = 0; t < TT; t++)
        k_rec_step<1><<<192, 256>>>(t, ba);
    k_attn_tail<<<BB, 256>>>(TT - 1, ba);

    // hc -> bf16 hi/lo, then batched logits (A = Wd rows, B = hc rows)
    {
        int n4 = (int)((size_t)BB * TT * U2 / 4);
        k_split4<<<(n4 + 255) / 256, 256>>>((const float4*)pHc,
            (__nv_bfloat162*)pHcHi, (__nv_bfloat162*)pHcLo, n4);
    }
    k_hmma<1><<<dim3((BB * TT) / 128, VD_ / 128), 256, SMEM_DYN>>>(
        pWdHi, pWdLo, pHcHi, pHcLo, bd, nullptr, out, VD_, BB * TT, U2);
}

// round 11
// speedup vs baseline: 1.0007x; 1.0007x over previous
#include <cuda_runtime.h>
#include <cuda_bf16.h>
#include <math.h>
#include <stdint.h>

// ---------------- problem constants ----------------
#define BB   64
#define SS   64
#define TT   32
#define EE   512
#define UU   1024
#define G4   (4*UU)      // 4096
#define U2   (2*UU)      // 2048
#define VD_  32000

// ---------------- device scratch (allocation-free contract) ----------------
__device__ __nv_bfloat16 g_XembEHi[BB*SS*EE];
__device__ __nv_bfloat16 g_XembELo[BB*SS*EE];
__device__ __nv_bfloat16 g_XembDHi[BB*TT*EE];
__device__ __nv_bfloat16 g_XembDLo[BB*TT*EE];
__device__ __nv_bfloat16 g_WeHi[G4*EE];
__device__ __nv_bfloat16 g_WeLo[G4*EE];
__device__ __nv_bfloat16 g_WidHi[G4*EE];
__device__ __nv_bfloat16 g_WidLo[G4*EE];
__device__ __nv_bfloat16 g_WdHi[(size_t)VD_*U2];
__device__ __nv_bfloat16 g_WdLo[(size_t)VD_*U2];
__device__ __nv_bfloat16 g_hcHi[(size_t)BB*TT*U2];
__device__ __nv_bfloat16 g_hcLo[(size_t)BB*TT*U2];

// recurrence: reordered bf16 weights (CTA-sliced, gate-interleaved rows)
__device__ __nv_bfloat16 g_WreHi[(size_t)G4*UU];          // enc: row' = cta*32 + g*8 + uu
__device__ __nv_bfloat16 g_WreLo[(size_t)G4*UU];
__device__ __nv_bfloat16 g_WrdHi[(size_t)(UU+G4)*UU];     // dec: row' = cta*40 + [q:0..7 | 8+g*8+uu]
__device__ __nv_bfloat16 g_WrdLo[(size_t)(UU+G4)*UU];
// h double-buffered by step parity: read [par], write [par^1]
__device__ __nv_bfloat16 g_hHi[2][BB*UU];
__device__ __nv_bfloat16 g_hLo[2][BB*UU];

__device__ float g_Xe[(size_t)BB*SS*G4];            // x@W_ih_e^T + biases
__device__ float g_Xd[(size_t)BB*TT*G4];
__device__ float g_o [(size_t)BB*SS*UU];            // encoder outputs (fp32, for attention)
__device__ float g_c [BB*UU];
__device__ float g_q [2][BB*UU];                    // double-buffered q = h@Wa^T
__device__ float g_hc[(size_t)BB*TT*U2];            // [b*T+t][ctx|h]

// ---------------- helpers ----------------
__device__ __forceinline__ float sigf(float x) { return 1.f / (1.f + expf(-x)); }

__device__ __forceinline__ void cp16(void* dst, const void* src) {
    uint32_t a;
    asm("{ .reg .u64 t; cvta.to.shared.u64 t, %1; cvt.u32.u64 %0, t; }"
        : "=r"(a) : "l"(dst));
    asm volatile("cp.async.cg.shared.global [%0], [%1], 16;" :: "r"(a), "l"(src));
}

__device__ __forceinline__ void mma16816(float* c, const uint32_t* a, const uint32_t* b) {
    asm volatile(
        "mma.sync.aligned.m16n8k16.row.col.f32.bf16.bf16.f32 "
        "{%0,%1,%2,%3}, {%4,%5,%6,%7}, {%8,%9}, {%0,%1,%2,%3};"
        : "+f"(c[0]), "+f"(c[1]), "+f"(c[2]), "+f"(c[3])
        : "r"(a[0]), "r"(a[1]), "r"(a[2]), "r"(a[3]), "r"(b[0]), "r"(b[1]));
}

__device__ __forceinline__ void split1(float x, __nv_bfloat16& h, __nv_bfloat16& l) {
    h = __float2bfloat16(x);
    l = __float2bfloat16(x - __bfloat162float(h));
}

// ---------------- generic fp32 -> bf16 hi/lo split ----------------
__global__ void k_split4(const float4* __restrict__ src,
                         __nv_bfloat162* __restrict__ hi,
                         __nv_bfloat162* __restrict__ lo, int n4)
{
    int gid = blockIdx.x * blockDim.x + threadIdx.x;
    if (gid >= n4) return;
    float4 v = src[gid];
    __nv_bfloat16 hx, hy, hz, hw, lx, ly, lz, lw;
    split1(v.x, hx, lx); split1(v.y, hy, ly);
    split1(v.z, hz, lz); split1(v.w, hw, lw);
    __nv_bfloat162 a; a.x = hx; a.y = hy;
    __nv_bfloat162 b; b.x = hz; b.y = hw;
    __nv_bfloat162 c; c.x = lx; c.y = ly;
    __nv_bfloat162 d; d.x = lz; d.y = lw;
    hi[gid * 2] = a; hi[gid * 2 + 1] = b;
    lo[gid * 2] = c; lo[gid * 2 + 1] = d;
}

// ---------------- reorder + split for recurrence weights ----------------
__global__ void k_split_reord_enc(const float4* __restrict__ W) {
    int gid = blockIdx.x * blockDim.x + threadIdx.x;   // G4 * 256
    int rp = gid >> 8, c = gid & 255;
    int cta = rp >> 5, rr = rp & 31;
    int g = rr >> 3, uu = rr & 7;
    int orig = g * UU + cta * 8 + uu;
    float4 v = W[(size_t)orig * 256 + c];
    __nv_bfloat16 hx, hy, hz, hw, lx, ly, lz, lw;
    split1(v.x, hx, lx); split1(v.y, hy, ly);
    split1(v.z, hz, lz); split1(v.w, hw, lw);
    __nv_bfloat162 a; a.x = hx; a.y = hy;
    __nv_bfloat162 b; b.x = hz; b.y = hw;
    __nv_bfloat162 cc; cc.x = lx; cc.y = ly;
    __nv_bfloat162 dd; dd.x = lz; dd.y = lw;
    ((__nv_bfloat162*)g_WreHi)[gid * 2] = a; ((__nv_bfloat162*)g_WreHi)[gid * 2 + 1] = b;
    ((__nv_bfloat162*)g_WreLo)[gid * 2] = cc; ((__nv_bfloat162*)g_WreLo)[gid * 2 + 1] = dd;
}

__global__ void k_split_reord_dec(const float4* __restrict__ Wa,
                                  const float4* __restrict__ Whh) {
    int gid = blockIdx.x * blockDim.x + threadIdx.x;   // (UU+G4) * 256
    int rp = gid >> 8, c = gid & 255;
    int cta = rp / 40, rr = rp % 40;
    const float4* src;
    int orig;
    if (rr < 8) { src = Wa;  orig = cta * 8 + rr; }
    else {
        int g = (rr - 8) >> 3, uu = (rr - 8) & 7;
        src = Whh; orig = g * UU + cta * 8 + uu;
    }
    float4 v = src[(size_t)orig * 256 + c];
    __nv_bfloat16 hx, hy, hz, hw, lx, ly, lz, lw;
    split1(v.x, hx, lx); split1(v.y, hy, ly);
    split1(v.z, hz, lz); split1(v.w, hw, lw);
    __nv_bfloat162 a; a.x = hx; a.y = hy;
    __nv_bfloat162 b; b.x = hz; b.y = hw;
    __nv_bfloat162 cc; cc.x = lx; cc.y = ly;
    __nv_bfloat162 dd; dd.x = lz; dd.y = lw;
    ((__nv_bfloat162*)g_WrdHi)[gid * 2] = a; ((__nv_bfloat162*)g_WrdHi)[gid * 2 + 1] = b;
    ((__nv_bfloat162*)g_WrdLo)[gid * 2] = cc; ((__nv_bfloat162*)g_WrdLo)[gid * 2 + 1] = dd;
}

// ---------------- embedding gathers (write bf16 hi/lo) ----------------
__global__ void k_gather_enc(const int* __restrict__ x, const float* __restrict__ emb) {
    int gid = blockIdx.x * blockDim.x + threadIdx.x;      // BB*SS*(EE/4)
    const int E4 = EE / 4;
    int r = gid / E4, c = gid % E4;
    float4 v = ((const float4*)emb)[(size_t)x[r] * E4 + c];
    __nv_bfloat16 hx, hy, hz, hw, lx, ly, lz, lw;
    split1(v.x, hx, lx); split1(v.y, hy, ly);
    split1(v.z, hz, lz); split1(v.w, hw, lw);
    size_t pi = (size_t)r * (EE / 2) + c * 2;
    __nv_bfloat162 a; a.x = hx; a.y = hy; ((__nv_bfloat162*)g_XembEHi)[pi] = a;
    __nv_bfloat162 b; b.x = hz; b.y = hw; ((__nv_bfloat162*)g_XembEHi)[pi + 1] = b;
    __nv_bfloat162 cc; cc.x = lx; cc.y = ly; ((__nv_bfloat162*)g_XembELo)[pi] = cc;
    __nv_bfloat162 dd; dd.x = lz; dd.y = lw; ((__nv_bfloat162*)g_XembELo)[pi + 1] = dd;
}

__global__ void k_gather_dec(const int* __restrict__ y, const float* __restrict__ emb) {
    int gid = blockIdx.x * blockDim.x + threadIdx.x;      // BB*TT*(EE/4)
    const int E4 = EE / 4;
    int r = gid / E4, c = gid % E4;
    int b = r / TT, t = r % TT;
    int id = y[b * (TT + 1) + t];
    float4 v = ((const float4*)emb)[(size_t)id * E4 + c];
    __nv_bfloat16 hx, hy, hz, hw, lx, ly, lz, lw;
    split1(v.x, hx, lx); split1(v.y, hy, ly);
    split1(v.z, hz, lz); split1(v.w, hw, lw);
    size_t pi = (size_t)r * (EE / 2) + c * 2;
    __nv_bfloat162 a; a.x = hx; a.y = hy; ((__nv_bfloat162*)g_XembDHi)[pi] = a;
    __nv_bfloat162 b2; b2.x = hz; b2.y = hw; ((__nv_bfloat162*)g_XembDHi)[pi + 1] = b2;
    __nv_bfloat162 cc; cc.x = lx; cc.y = ly; ((__nv_bfloat162*)g_XembDLo)[pi] = cc;
    __nv_bfloat162 dd; dd.x = lz; dd.y = lw; ((__nv_bfloat162*)g_XembDLo)[pi + 1] = dd;
}

__global__ void k_init_state() {
    int gid = blockIdx.x * blockDim.x + threadIdx.x;
    if (gid < BB * UU) {
        g_c[gid] = 0.f;
        g_hHi[0][gid] = __float2bfloat16(0.f);
        g_hLo[0][gid] = __float2bfloat16(0.f);
        g_hHi[1][gid] = __float2bfloat16(0.f);
        g_hLo[1][gid] = __float2bfloat16(0.f);
    }
}

// ---------------- HMMA bf16x2-compensated GEMM (big, 128x128 tile) ----------------
#define PITCH   80
#define ARR_SZ  (128 * PITCH)           // 10240
#define STG_SZ  (4 * ARR_SZ)            // 40960
#define OFF_AHI 0
#define OFF_ALO ARR_SZ
#define OFF_BHI (2 * ARR_SZ)
#define OFF_BLO (3 * ARR_SZ)
#define SMEM_DYN (2 * STG_SZ)           // 80 KB

template <int MODE>
__global__ void __launch_bounds__(256)
k_hmma(const __nv_bfloat16* __restrict__ Ahi, const __nv_bfloat16* __restrict__ Alo,
       const __nv_bfloat16* __restrict__ Bhi, const __nv_bfloat16* __restrict__ Blo,
       const float* __restrict__ bias1, const float* __restrict__ bias2,
       float* __restrict__ C, int M, int N, int K)
{
    extern __shared__ __align__(16) char smem[];

    const int tid = threadIdx.x;
    const int wid = tid >> 5, lane = tid & 31;
    const int gq = lane >> 2, tq = lane & 3;
    const int wm = (wid >> 2) * 64;
    const int wn = (wid & 3) * 32;
    const int bm = blockIdx.y * 128, bn = blockIdx.x * 128;
    const int nk = K >> 5;

    const __nv_bfloat16* gsrc[4] = {Ahi, Alo, Bhi, Blo};

    auto load_stage = [&](int kc) {
        char* base = smem + (kc & 1) * STG_SZ;
        int k0 = kc << 5;
#pragma unroll
        for (int i = 0; i < 8; i++) {
            int e = tid + i * 256;
            int arr = e >> 9;
            int r = (e >> 2) & 127;
            int seg = e & 3;
            int grow = (arr < 2 ? bm : bn) + r;
            const __nv_bfloat16* src = gsrc[arr] + (size_t)grow * K + k0 + seg * 8;
            cp16(base + arr * ARR_SZ + r * PITCH + seg * 16, src);
        }
        asm volatile("cp.async.commit_group;");
    };

    float acc[4][4][4];
#pragma unroll
    for (int i = 0; i < 4; i++)
#pragma unroll
        for (int j = 0; j < 4; j++)
#pragma unroll
            for (int q = 0; q < 4; q++) acc[i][j][q] = 0.f;

    load_stage(0);

    for (int kc = 0; kc < nk; kc++) {
        if (kc + 1 < nk) {
            load_stage(kc + 1);
            asm volatile("cp.async.wait_group 1;");
        } else {
            asm volatile("cp.async.wait_group 0;");
        }
        __syncthreads();

        const char* base = smem + (kc & 1) * STG_SZ;
#pragma unroll
        for (int kk = 0; kk < 2; kk++) {
            const int kb = kk * 32;
            uint32_t ah[4][4], al[4][4], bh[4][2], bl[4][2];
#pragma unroll
            for (int i = 0; i < 4; i++) {
                int r0 = wm + i * 16 + gq;
                const char* pa = base + kb + 4 * tq;
                ah[i][0] = *(const uint32_t*)(pa + OFF_AHI + r0 * PITCH);
                ah[i][1] = *(const uint32_t*)(pa + OFF_AHI + (r0 + 8) * PITCH);
                ah[i][2] = *(const uint32_t*)(pa + OFF_AHI + r0 * PITCH + 16);
                ah[i][3] = *(const uint32_t*)(pa + OFF_AHI + (r0 + 8) * PITCH + 16);
                al[i][0] = *(const uint32_t*)(pa + OFF_ALO + r0 * PITCH);
                al[i][1] = *(const uint32_t*)(pa + OFF_ALO + (r0 + 8) * PITCH);
                al[i][2] = *(const uint32_t*)(pa + OFF_ALO + r0 * PITCH + 16);
                al[i][3] = *(const uint32_t*)(pa + OFF_ALO + (r0 + 8) * PITCH + 16);
            }
#pragma unroll
            for (int j = 0; j < 4; j++) {
                int rb = wn + j * 8 + gq;
                const char* pb = base + kb + 4 * tq;
                bh[j][0] = *(const uint32_t*)(pb + OFF_BHI + rb * PITCH);
                bh[j][1] = *(const uint32_t*)(pb + OFF_BHI + rb * PITCH + 16);
                bl[j][0] = *(const uint32_t*)(pb + OFF_BLO + rb * PITCH);
                bl[j][1] = *(const uint32_t*)(pb + OFF_BLO + rb * PITCH + 16);
            }
#pragma unroll
            for (int i = 0; i < 4; i++)
#pragma unroll
                for (int j = 0; j < 4; j++) {
                    mma16816(acc[i][j], ah[i], bh[j]);
                    mma16816(acc[i][j], ah[i], bl[j]);
                    mma16816(acc[i][j], al[i], bh[j]);
                }
        }
        __syncthreads();
    }

#pragma unroll
    for (int i = 0; i < 4; i++) {
        int r0 = bm + wm + i * 16 + gq;
        if (MODE == 0) {
#pragma unroll
            for (int j = 0; j < 4; j++) {
                int col = bn + wn + j * 8 + 2 * tq;
                float b0 = bias1[col] + (bias2 ? bias2[col] : 0.f);
                float b1 = bias1[col + 1] + (bias2 ? bias2[col + 1] : 0.f);
                float2 v0 = make_float2(acc[i][j][0] + b0, acc[i][j][1] + b1);
                float2 v1 = make_float2(acc[i][j][2] + b0, acc[i][j][3] + b1);
                *(float2*)(C + (size_t)r0 * N + col) = v0;
                *(float2*)(C + (size_t)(r0 + 8) * N + col) = v1;
            }
        } else {
            float bv0 = bias1[r0];
            float bv1 = bias1[r0 + 8];
#pragma unroll
            for (int j = 0; j < 4; j++) {
                int col = bn + wn + j * 8 + 2 * tq;
                int b = col >> 5, t = col & 31;
                float* p0 = C + ((size_t)b * VD_ + r0) * 32 + t;
                float* p1 = C + ((size_t)b * VD_ + r0 + 8) * 32 + t;
                *(float2*)p0 = make_float2(acc[i][j][0] + bv0, acc[i][j][1] + bv0);
                *(float2*)p1 = make_float2(acc[i][j][2] + bv1, acc[i][j][3] + bv1);
            }
        }
    }
}

// ---------------- attention body (shared by decoder step + tail) ----------------
__device__ __forceinline__ void attn_body(int b, int ta, const float* __restrict__ ba,
                                          float* scratch)
{
    float* qs = scratch;          // 1024
    float* sc = scratch + UU;     // 65 (sc[SS] holds 1/sum)
    int tid = threadIdx.x;

    const float* qrow = g_q[ta & 1] + (size_t)b * UU;
    for (int u = tid; u < UU; u += 256) qs[u] = qrow[u] + ba[u];
    __syncthreads();

    int w = tid >> 5, lane = tid & 31;
    const float* ob = g_o + (size_t)b * SS * UU;
    for (int s = w; s < SS; s += 8) {
        const float* os = ob + (size_t)s * UU;
        float acc = 0.f;
        for (int u = lane; u < UU; u += 32) acc = fmaf(qs[u], os[u], acc);
#pragma unroll
        for (int off = 16; off; off >>= 1) acc += __shfl_xor_sync(0xffffffffu, acc, off);
        if (lane == 0) sc[s] = acc;
    }
    __syncthreads();

    if (tid == 0) {
        float mx = sc[0];
#pragma unroll
        for (int s = 1; s < SS; s++) mx = fmaxf(mx, sc[s]);
        float sum = 0.f;
        for (int s = 0; s < SS; s++) { float e = expf(sc[s] - mx); sc[s] = e; sum += e; }
        sc[SS] = 1.f / sum;
    }
    __syncthreads();
    float inv = sc[SS];

    float* hcrow = g_hc + (size_t)(b * TT + ta) * U2;
    for (int u = tid; u < UU; u += 256) {
        float acc = 0.f;
#pragma unroll 8
        for (int s = 0; s < SS; s++) acc = fmaf(sc[s] * inv, ob[(size_t)s * UU + u], acc);
        hcrow[u] = acc;
    }
}

// ---------------- fused recurrence step: GEMM + gate (+ attention riders) ----------
// 4-stage cp.async pipeline (prefetch distance 3) hides L2 latency per chunk.
// MODE 0 (encoder): grid 128, NR=32. MODE 1 (decoder): grid 192, NR=40, blocks
// 128..191 run attention for step t-1. h double-buffered by parity.
template <int MODE>
__global__ void __launch_bounds__(256)
k_rec_step(int t, const float* __restrict__ ba)
{
    constexpr int NR  = MODE ? 40 : 32;
    constexpr int STG = (128 + 2 * NR) * 80;     // bytes per stage
    constexpr int OALO = 64 * 80;                // 5120
    constexpr int OBHI = 128 * 80;               // 10240
    constexpr int TOT = 512 + NR * 8;            // cp16 ops per stage
    constexpr int NK  = 32;

    extern __shared__ __align__(16) char dsm[];

    const int tid = threadIdx.x;
    const int par = t & 1;

    if (MODE == 1 && blockIdx.x >= 128) {
        if (t == 0) return;
        attn_body(blockIdx.x - 128, t - 1, ba, (float*)dsm);
        return;
    }

    float* zs = (float*)(dsm + 4 * STG);         // 64*33 floats

    const int cta = blockIdx.x;
    const int wid = tid >> 5, lane = tid & 31;
    const int gq = lane >> 2, tq = lane & 3;
    const int mh = wid >> 2, nc = wid & 3;

    const __nv_bfloat16* Whi = MODE ? g_WrdHi : g_WreHi;
    const __nv_bfloat16* Wlo = MODE ? g_WrdLo : g_WreLo;
    const __nv_bfloat16* hHi = g_hHi[par];
    const __nv_bfloat16* hLo = g_hLo[par];
    const size_t wbase = (size_t)cta * NR * UU;

    auto load_stage = [&](int kc) {
        char* base = dsm + (kc & 3) * STG;
        int k0 = kc << 5;
#pragma unroll
        for (int i = 0; i < (TOT + 255) / 256; i++) {
            int e = tid + i * 256;
            if (e < TOT) {
                const __nv_bfloat16* src; char* dst;
                if (e < 512) {
                    int arr = e >> 8, r = (e >> 2) & 63, seg = e & 3;
                    src = (arr ? hLo : hHi) + r * UU + k0 + seg * 8;
                    dst = base + arr * OALO + r * 80 + seg * 16;
                } else {
                    int e2 = e - 512;
                    int arr = e2 >= NR * 4;
                    int idx = e2 - arr * NR * 4;
                    int r = idx >> 2, seg = idx & 3;
                    src = (arr ? Wlo : Whi) + wbase + (size_t)r * UU + k0 + seg * 8;
                    dst = base + OBHI + arr * (NR * 80) + r * 80 + seg * 16;
                }
                cp16(dst, src);
            }
        }
        asm volatile("cp.async.commit_group;");
    };

    float accz[2][4] = {};
    float accq[4] = {};

    // prologue: 3 stages in flight
    load_stage(0);
    load_stage(1);
    load_stage(2);

    for (int kc = 0; kc < NK; kc++) {
        if (kc + 3 < NK) load_stage(kc + 3);
        else             asm volatile("cp.async.commit_group;");   // keep group count uniform
        asm volatile("cp.async.wait_group 3;");
        __syncthreads();

        const char* base = dsm + (kc & 3) * STG;
#pragma unroll
        for (int kk = 0; kk < 2; kk++) {
            const int kb = kk * 32;
            const char* pa = base + kb + 4 * tq;
            uint32_t ah[2][4], al[2][4];
#pragma unroll
            for (int i = 0; i < 2; i++) {
                int r0 = mh * 32 + i * 16 + gq;
                ah[i][0] = *(const uint32_t*)(pa + r0 * 80);
                ah[i][1] = *(const uint32_t*)(pa + (r0 + 8) * 80);
                ah[i][2] = *(const uint32_t*)(pa + r0 * 80 + 16);
                ah[i][3] = *(const uint32_t*)(pa + (r0 + 8) * 80 + 16);
                al[i][0] = *(const uint32_t*)(pa + OALO + r0 * 80);
                al[i][1] = *(const uint32_t*)(pa + OALO + (r0 + 8) * 80);
                al[i][2] = *(const uint32_t*)(pa + OALO + r0 * 80 + 16);
                al[i][3] = *(const uint32_t*)(pa + OALO + (r0 + 8) * 80 + 16);
            }
            {   // z tile: B row = (MODE? 8:0) + nc*8 + gq
                int rb = (MODE ? 8 : 0) + nc * 8 + gq;
                const char* pb = base + OBHI + rb * 80 + kb + 4 * tq;
                uint32_t bh[2], bl[2];
                bh[0] = *(const uint32_t*)(pb);
                bh[1] = *(const uint32_t*)(pb + 16);
                bl[0] = *(const uint32_t*)(pb + NR * 80);
                bl[1] = *(const uint32_t*)(pb + NR * 80 + 16);
#pragma unroll
                for (int i = 0; i < 2; i++) {
                    mma16816(accz[i], ah[i], bh);
                    mma16816(accz[i], ah[i], bl);
                    mma16816(accz[i], al[i], bh);
                }
            }
            if (MODE == 1 && nc < 2) {   // q tile: B rows 0..7, A frag = ah[nc]
                const char* pb = base + OBHI + gq * 80 + kb + 4 * tq;
                uint32_t bh[2], bl[2];
                bh[0] = *(const uint32_t*)(pb);
                bh[1] = *(const uint32_t*)(pb + 16);
                bl[0] = *(const uint32_t*)(pb + NR * 80);
                bl[1] = *(const uint32_t*)(pb + NR * 80 + 16);
                mma16816(accq, ah[nc], bh);
                mma16816(accq, ah[nc], bl);
                mma16816(accq, al[nc], bh);
            }
        }
        __syncthreads();
    }

    // ---- z -> SMEM ----
#pragma unroll
    for (int i = 0; i < 2; i++) {
        int b0 = mh * 32 + i * 16 + gq;
        int col = nc * 8 + 2 * tq;
        zs[b0 * 33 + col]           = accz[i][0];
        zs[b0 * 33 + col + 1]       = accz[i][1];
        zs[(b0 + 8) * 33 + col]     = accz[i][2];
        zs[(b0 + 8) * 33 + col + 1] = accz[i][3];
    }
    // ---- q -> global (decoder) ----
    if (MODE == 1 && nc < 2) {
        int f = mh * 2 + nc;
        int b0 = f * 16 + gq;
        int u0 = cta * 8 + 2 * tq;
        *(float2*)&g_q[t & 1][b0 * UU + u0]       = make_float2(accq[0], accq[1]);
        *(float2*)&g_q[t & 1][(b0 + 8) * UU + u0] = make_float2(accq[2], accq[3]);
    }
    __syncthreads();

    // ---- gate: 2 (b,uu) per thread ----
#pragma unroll
    for (int rep = 0; rep < 2; rep++) {
        int idx = tid + rep * 256;      // 0..511
        int b = idx >> 3, uu = idx & 7;
        int u = cta * 8 + uu;
        const float* xrow = MODE ? (g_Xd + (size_t)(b * TT + t) * G4)
                                 : (g_Xe + (size_t)(b * SS + t) * G4);
        float zi = zs[b * 33 + uu]      + xrow[u];
        float zf = zs[b * 33 + 8 + uu]  + xrow[UU + u];
        float zg = zs[b * 33 + 16 + uu] + xrow[2 * UU + u];
        float zo = zs[b * 33 + 24 + uu] + xrow[3 * UU + u];
        float c = g_c[b * UU + u];
        float cn = sigf(zf) * c + sigf(zi) * tanhf(zg);
        float hn = sigf(zo) * tanhf(cn);
        g_c[b * UU + u] = cn;
        __nv_bfloat16 hh, hl; split1(hn, hh, hl);
        g_hHi[par ^ 1][b * UU + u] = hh;
        g_hLo[par ^ 1][b * UU + u] = hl;
        if (MODE == 1) g_hc[(size_t)(b * TT + t) * U2 + UU + u] = hn;
        else           g_o [(size_t)(b * SS + t) * UU + u] = hn;
    }
}

__global__ void __launch_bounds__(256) k_attn_tail(int ta, const float* __restrict__ ba)
{
    __shared__ float scratch[1100];
    attn_body(blockIdx.x, ta, ba, scratch);
}

// ---------------- launch ----------------
extern "C" void kernel_launch(void* const* d_in, const int* in_sizes, int n_in,
                              void* d_out, int out_size)
{
    const int*   x       = (const int*)d_in[0];
    const int*   y       = (const int*)d_in[1];
    const float* enc_emb = (const float*)d_in[2];
    const float* dec_emb = (const float*)d_in[3];
    const float* W_ih_e  = (const float*)d_in[4];
    const float* W_hh_e  = (const float*)d_in[5];
    const float* b_ih_e  = (const float*)d_in[6];
    const float* b_hh_e  = (const float*)d_in[7];
    const float* Wa      = (const float*)d_in[8];
    const float* ba      = (const float*)d_in[9];
    const float* W_ih_d  = (const float*)d_in[10];
    const float* W_hh_d  = (const float*)d_in[11];
    const float* b_ih_d  = (const float*)d_in[12];
    const float* b_hh_d  = (const float*)d_in[13];
    const float* Wd      = (const float*)d_in[14];
    const float* bd      = (const float*)d_in[15];
    float* out = (float*)d_out;

    float *pXe, *pXd, *pHc;
    __nv_bfloat16 *pXeHi, *pXeLo, *pXdHi, *pXdLo, *pWeHi, *pWeLo, *pWidHi, *pWidLo;
    __nv_bfloat16 *pWdHi, *pWdLo, *pHcHi, *pHcLo;
    cudaGetSymbolAddress((void**)&pXe, g_Xe);
    cudaGetSymbolAddress((void**)&pXd, g_Xd);
    cudaGetSymbolAddress((void**)&pHc, g_hc);
    cudaGetSymbolAddress((void**)&pXeHi, g_XembEHi);
    cudaGetSymbolAddress((void**)&pXeLo, g_XembELo);
    cudaGetSymbolAddress((void**)&pXdHi, g_XembDHi);
    cudaGetSymbolAddress((void**)&pXdLo, g_XembDLo);
    cudaGetSymbolAddress((void**)&pWeHi, g_WeHi);
    cudaGetSymbolAddress((void**)&pWeLo, g_WeLo);
    cudaGetSymbolAddress((void**)&pWidHi, g_WidHi);
    cudaGetSymbolAddress((void**)&pWidLo, g_WidLo);
    cudaGetSymbolAddress((void**)&pWdHi, g_WdHi);
    cudaGetSymbolAddress((void**)&pWdLo, g_WdLo);
    cudaGetSymbolAddress((void**)&pHcHi, g_hcHi);
    cudaGetSymbolAddress((void**)&pHcLo, g_hcLo);

    cudaFuncSetAttribute(k_hmma<0>, cudaFuncAttributeMaxDynamicSharedMemorySize, SMEM_DYN);
    cudaFuncSetAttribute(k_hmma<1>, cudaFuncAttributeMaxDynamicSharedMemorySize, SMEM_DYN);
    // rec-step dynamic smem: 4 stages + zs
    const int RSM0 = 4 * ((128 + 64) * 80) + 64 * 33 * 4;   // 69888
    const int RSM1 = 4 * ((128 + 80) * 80) + 64 * 33 * 4;   // 75008
    cudaFuncSetAttribute(k_rec_step<0>, cudaFuncAttributeMaxDynamicSharedMemorySize, RSM0);
    cudaFuncSetAttribute(k_rec_step<1>, cudaFuncAttributeMaxDynamicSharedMemorySize, RSM1);

    // embeddings + init + weight splits
    k_gather_enc<<<BB * SS * (EE / 4) / 256, 256>>>(x, enc_emb);
    k_gather_dec<<<BB * TT * (EE / 4) / 256, 256>>>(y, dec_emb);
    k_init_state<<<BB * UU / 256, 256>>>();
    {
        int n4 = G4 * EE / 4;
        k_split4<<<(n4 + 255) / 256, 256>>>((const float4*)W_ih_e,
            (__nv_bfloat162*)pWeHi, (__nv_bfloat162*)pWeLo, n4);
        k_split4<<<(n4 + 255) / 256, 256>>>((const float4*)W_ih_d,
            (__nv_bfloat162*)pWidHi, (__nv_bfloat162*)pWidLo, n4);
    }
    // recurrence weights: reorder + split
    k_split_reord_enc<<<G4 * 256 / 256, 256>>>((const float4*)W_hh_e);
    k_split_reord_dec<<<(UU + G4) * 256 / 256, 256>>>((const float4*)Wa,
                                                      (const float4*)W_hh_d);
    {
        int n4 = (int)((size_t)VD_ * U2 / 4);
        k_split4<<<(n4 + 255) / 256, 256>>>((const float4*)Wd,
            (__nv_bfloat162*)pWdHi, (__nv_bfloat162*)pWdLo, n4);
    }

    // time-batched input projections (tensor pipe)
    k_hmma<0><<<dim3(G4 / 128, (BB * SS) / 128), 256, SMEM_DYN>>>(
        pXeHi, pXeLo, pWeHi, pWeLo, b_ih_e, b_hh_e, pXe, BB * SS, G4, EE);
    k_hmma<0><<<dim3(G4 / 128, (BB * TT) / 128), 256, SMEM_DYN>>>(
        pXdHi, pXdLo, pWidHi, pWidLo, b_ih_d, b_hh_d, pXd, BB * TT, G4, EE);

    // encoder: one fused GEMM+gate launch per step (4-stage pipelined)
    for (int t = 0; t < SS; t++)
        k_rec_step<0><<<128, 256, RSM0>>>(t, ba);

    // decoder: one launch per step (GEMM+gate blocks + attention riders for t-1)
    for (int t = 0; t < TT; t++)
        k_rec_step<1><<<192, 256, RSM1>>>(t, ba);
    k_attn_tail<<<BB, 256>>>(TT - 1, ba);

    // hc -> bf16 hi/lo, then batched logits (A = Wd rows, B = hc rows)
    {
        int n4 = (int)((size_t)BB * TT * U2 / 4);
        k_split4<<<(n4 + 255) / 256, 256>>>((const float4*)pHc,
            (__nv_bfloat162*)pHcHi, (__nv_bfloat162*)pHcLo, n4);
    }
    k_hmma<1><<<dim3((BB * TT) / 128, VD_ / 128), 256, SMEM_DYN>>>(
        pWdHi, pWdLo, pHcHi, pHcLo, bd, nullptr, out, VD_, BB * TT, U2);
}